// round 11
// baseline (speedup 1.0000x reference)
#include <cuda_runtime.h>
#include <cuda_fp16.h>
#include <cstdint>
#include <cstddef>

// ---------------- problem constants ----------------
#define BB   8
#define CC   512
#define HH   48
#define HW   2304     // 48*48
#define HOS  24       // stride-2 output spatial
#define HWS  576      // 24*24
#define HWSP 640      // padded N for 128-tiles
#define KCV  4608     // 512*9 (im2col K)
#define OCQ  1024     // 2C
#define MQK  1536     // combined conv output rows (2C + C)
#define DD   64       // C/8
#define DD2  128      // combined qp+kp rows

// ---------------- scratch (device globals; allocation-free) ----------------
__device__ __align__(128) __half g_col_h[(size_t)BB * HWSP * KCV];
__device__ __align__(128) __half g_col_l[(size_t)BB * HWSP * KCV];
__device__ __align__(128) __half g_wq_h[(size_t)MQK * KCV];
__device__ __align__(128) __half g_wq_l[(size_t)MQK * KCV];
__device__ float  g_bias[MQK];
__device__ __align__(128) __half g_wp_h[(size_t)DD2 * CC];
__device__ __align__(128) __half g_wp_l[(size_t)DD2 * CC];
__device__ float  g_bias2[DD2];
__device__ __align__(128) __half g_qk_h[(size_t)BB * MQK * HWSP];
__device__ __align__(128) __half g_qk_l[(size_t)BB * MQK * HWSP];
__device__ __align__(128) float  g_attn_c[(size_t)BB * OCQ * CC];   // energies
__device__ __align__(128) __half g_ac_h[(size_t)BB * OCQ * CC];
__device__ __align__(128) __half g_ac_l[(size_t)BB * OCQ * CC];
__device__ __align__(128) __half g_xt_h[(size_t)BB * HW * CC];
__device__ __align__(128) __half g_xt_l[(size_t)BB * HW * CC];
__device__ __align__(128) __half g_oc_h[(size_t)BB * OCQ * HW];
__device__ __align__(128) float  g_qpkp[(size_t)BB * DD2 * HW];
__device__ __align__(128) __half g_qpt_h[(size_t)BB * HW * DD];
__device__ __align__(128) __half g_qpt_l[(size_t)BB * HW * DD];
__device__ __align__(128) __half g_kpt_h[(size_t)BB * HW * DD];
__device__ __align__(128) __half g_kpt_l[(size_t)BB * HW * DD];
__device__ __align__(128) float  g_attn_p[(size_t)BB * HW * HW];    // energies
__device__ __align__(128) __half g_ap_h[(size_t)BB * HW * HW];

// ---------------- helpers ----------------
__device__ __forceinline__ void split2(float v, __half& h, __half& l) {
    h = __float2half_rn(v);
    l = __float2half_rn(v - __half2float(h));
}
__device__ __forceinline__ void mma16816(float* c, const uint32_t* a,
                                         uint32_t b0, uint32_t b1) {
    asm volatile(
        "mma.sync.aligned.m16n8k16.row.col.f32.f16.f16.f32 "
        "{%0,%1,%2,%3},{%4,%5,%6,%7},{%8,%9},{%0,%1,%2,%3};"
        : "+f"(c[0]), "+f"(c[1]), "+f"(c[2]), "+f"(c[3])
        : "r"(a[0]), "r"(a[1]), "r"(a[2]), "r"(a[3]), "r"(b0), "r"(b1));
}
__device__ __forceinline__ void ldsm4(uint32_t* r, uint32_t addr) {
    asm volatile("ldmatrix.sync.aligned.m8n8.x4.shared.b16 {%0,%1,%2,%3}, [%4];"
        : "=r"(r[0]), "=r"(r[1]), "=r"(r[2]), "=r"(r[3]) : "r"(addr));
}
#define CP16(dst_u32, src_ptr) \
    asm volatile("cp.async.cg.shared.global [%0], [%1], 16;" :: "r"(dst_u32), "l"(src_ptr))
#define CP_COMMIT() asm volatile("cp.async.commit_group;" ::: "memory")

// ---------------- im2col (3x3 s2 p1) -> split fp16, [b][p][k], 4 k/thread ----------------
__global__ void im2col_split_k(const float* __restrict__ x) {
    const int KQ = KCV / 4;                       // 1152
    int idx = blockIdx.x * blockDim.x + threadIdx.x;
    int b = blockIdx.y;
    if (idx >= HWS * KQ) return;
    int p  = idx / KQ;
    int k0 = (idx - p * KQ) * 4;
    int oy = p / HOS, ox = p - oy * HOS;
    int iy0 = 2 * oy - 1, ix0 = 2 * ox - 1;
    const float* xb = x + (size_t)b * CC * HW;
    __half h[4], l[4];
    #pragma unroll
    for (int j = 0; j < 4; ++j) {
        int k = k0 + j;
        int ic = k / 9;
        int r  = k - ic * 9;
        int ky = r / 3, kx = r - ky * 3;
        int iy = iy0 + ky, ix = ix0 + kx;
        float v = 0.f;
        if ((unsigned)iy < (unsigned)HH && (unsigned)ix < (unsigned)HH)
            v = xb[((size_t)ic * HH + iy) * HH + ix];
        split2(v, h[j], l[j]);
    }
    size_t d = ((size_t)b * HWSP + p) * KCV + k0;
    *(__half2*)&g_col_h[d]     = __halves2half2(h[0], h[1]);
    *(__half2*)&g_col_h[d + 2] = __halves2half2(h[2], h[3]);
    *(__half2*)&g_col_l[d]     = __halves2half2(l[0], l[1]);
    *(__half2*)&g_col_l[d + 2] = __halves2half2(l[2], l[3]);
}

// ---------------- elementwise fp32 -> (hi, lo) fp16 (weights) ----------------
__global__ void split_f32_k(const float* __restrict__ s, __half* __restrict__ h,
                            __half* __restrict__ l, long long n) {
    long long i = (long long)blockIdx.x * blockDim.x + threadIdx.x;
    if (i >= n) return;
    __half hh, ll; split2(s[i], hh, ll);
    h[i] = hh; l[i] = ll;
}
__global__ void concat_bias_k(const float* a, const float* b, float* dst,
                              int na, int ntot) {
    int i = blockIdx.x * blockDim.x + threadIdx.x;
    if (i < na) dst[i] = a[i];
    else if (i < ntot) dst[i] = b[i - na];
}

// ---------------- tiled transpose + split: [R][Cn] fp32 -> [Cn][R] hi/lo ----------------
__global__ void transpose_split_k(const float* __restrict__ src,
                                  __half* __restrict__ oh, __half* __restrict__ ol,
                                  int R, int Cn, long long sIn, long long sOut) {
    __shared__ float tile[32][33];
    int b = blockIdx.z;
    src += (long long)b * sIn;
    oh  += (long long)b * sOut;
    ol  += (long long)b * sOut;
    int c0 = blockIdx.x * 32;
    int r0 = blockIdx.y * 32;
    int tx = threadIdx.x, ty = threadIdx.y;
    #pragma unroll
    for (int i = 0; i < 4; ++i)
        tile[ty + 8 * i][tx] = src[(long long)(r0 + ty + 8 * i) * Cn + c0 + tx];
    __syncthreads();
    #pragma unroll
    for (int i = 0; i < 4; ++i) {
        float v = tile[tx][ty + 8 * i];
        __half h, l; split2(v, h, l);
        long long o = (long long)(c0 + ty + 8 * i) * R + r0 + tx;
        oh[o] = h; ol[o] = l;
    }
}

// ---------------- split-fp16 tensor-core GEMM (ldmatrix, 8 warps) ----------------
// C = op(A)@op(B), A,B pre-split hi/lo fp16, stored [rows][K] K-contig.
// TERMS 3: AhBh+AlBh+AhBl ; 2: AhBh+AlBh ; 1: AhBh.
// Tile 128x128, BK=32, 256 threads (8 warps, 64x32 warp tiles), m16n8k16.
template <int TERMS, bool OF32, bool OSPLIT>
__global__ void __launch_bounds__(256, 2)
gemm_fp16(int M, int N, int K,
          const __half* __restrict__ Ah, const __half* __restrict__ Al,
          int lda, long long sA,
          const __half* __restrict__ Bh, const __half* __restrict__ Bl,
          int ldb, long long sB,
          float* __restrict__ Cf, int ldc, long long sC,
          __half* __restrict__ Ch, __half* __restrict__ Cl, long long sCh,
          const float* __restrict__ bias)
{
    constexpr int NA = (TERMS >= 2) ? 2 : 1;            // A comps
    constexpr int NB = (TERMS >= 3) ? 2 : 1;            // B comps
    constexpr int NCOMP = NA + NB;
    constexpr int MSZ = 128 * 40;                       // halves per component
    constexpr int SS  = NCOMP * MSZ;                    // halves per stage
    extern __shared__ __half sm[];

    int bz = blockIdx.z;
    Ah += (long long)bz * sA;
    if (TERMS >= 2) Al += (long long)bz * sA;
    Bh += (long long)bz * sB;
    if (TERMS >= 3) Bl += (long long)bz * sB;

    int m0 = blockIdx.y * 128;
    int n0 = blockIdx.x * 128;
    int tid  = threadIdx.x;
    int lane = tid & 31;
    int warp = tid >> 5;
    int wm = (warp >> 2) * 64;      // 2 warp-rows of 64
    int wn = (warp & 3) * 32;       // 4 warp-cols of 32
    int g = lane >> 2;
    int t = lane & 3;

    uint32_t smbase = (uint32_t)__cvta_generic_to_shared(sm);
    uint32_t a_loff = (uint32_t)(((lane & 7) + ((lane >> 3) & 1) * 8) * 40
                                 + (lane >> 4) * 8);
    uint32_t b_loff = (uint32_t)(((lane & 7) + (lane >> 4) * 8) * 40
                                 + ((lane >> 3) & 1) * 8);

    auto issue = [&](int stage, int k0) {
        #pragma unroll
        for (int j = 0; j < NCOMP * 2; ++j) {
            int q = j * 256 + tid;
            int comp = q >> 9;           // 512 16B-chunks per component
            int w = q & 511;
            int row = w >> 2, seg = w & 3;
            const __half* base;
            int ld, r0;
            if (comp < NA) { ld = lda; r0 = m0; base = (comp == 0) ? Ah : Al; }
            else           { ld = ldb; r0 = n0; base = (comp == NA) ? Bh : Bl; }
            const __half* src = base + (long long)(r0 + row) * ld + k0 + seg * 8;
            uint32_t dst = smbase +
                (uint32_t)(stage * SS + comp * MSZ + row * 40 + seg * 8) * 2;
            CP16(dst, src);
        }
    };

    float acc[4][4][4] = {};
    int nk = K / 32;

    issue(0, 0);
    CP_COMMIT();
    if (nk > 1) issue(1, 32);
    CP_COMMIT();

    for (int i = 0; i < nk; ++i) {
        if (i < nk - 1) asm volatile("cp.async.wait_group 1;" ::: "memory");
        else            asm volatile("cp.async.wait_group 0;" ::: "memory");
        __syncthreads();

        uint32_t st  = smbase + (uint32_t)((i & 1) * SS) * 2;
        uint32_t pAh = st;
        uint32_t pAl = st + (uint32_t)MSZ * 2;              // valid if NA==2
        uint32_t pBh = st + (uint32_t)(NA * MSZ) * 2;
        uint32_t pBl = st + (uint32_t)((NA + 1) * MSZ) * 2; // valid if NB==2

        #pragma unroll
        for (int kk = 0; kk < 32; kk += 16) {
            uint32_t ah[4][4], al[4][4];
            #pragma unroll
            for (int im = 0; im < 4; ++im) {
                uint32_t ro = (uint32_t)((wm + im * 16) * 40 + kk);
                ldsm4(ah[im], pAh + (ro + a_loff) * 2);
                if (TERMS >= 2) ldsm4(al[im], pAl + (ro + a_loff) * 2);
            }
            #pragma unroll
            for (int jp = 0; jp < 2; ++jp) {
                uint32_t co = (uint32_t)((wn + jp * 16) * 40 + kk);
                uint32_t bh[4], bl[4];
                ldsm4(bh, pBh + (co + b_loff) * 2);
                if (TERMS >= 3) ldsm4(bl, pBl + (co + b_loff) * 2);
                #pragma unroll
                for (int im = 0; im < 4; ++im) {
                    mma16816(acc[im][2 * jp],     ah[im], bh[0], bh[1]);
                    mma16816(acc[im][2 * jp + 1], ah[im], bh[2], bh[3]);
                    if (TERMS >= 2) {
                        mma16816(acc[im][2 * jp],     al[im], bh[0], bh[1]);
                        mma16816(acc[im][2 * jp + 1], al[im], bh[2], bh[3]);
                    }
                    if (TERMS >= 3) {
                        mma16816(acc[im][2 * jp],     ah[im], bl[0], bl[1]);
                        mma16816(acc[im][2 * jp + 1], ah[im], bl[2], bl[3]);
                    }
                }
            }
        }
        __syncthreads();
        if (i + 2 < nk) {
            issue((i + 2) & 1, (i + 2) * 32);
            CP_COMMIT();
        }
    }

    // ---------------- epilogue ----------------
    #pragma unroll
    for (int im = 0; im < 4; ++im) {
        int mr = m0 + wm + im * 16 + g;
        float bi0 = bias ? bias[mr] : 0.f;
        float bi1 = bias ? bias[mr + 8] : 0.f;
        #pragma unroll
        for (int jn = 0; jn < 4; ++jn) {
            int nc = n0 + wn + jn * 8 + 2 * t;
            float v00 = acc[im][jn][0] + bi0, v01 = acc[im][jn][1] + bi0;
            float v10 = acc[im][jn][2] + bi1, v11 = acc[im][jn][3] + bi1;
            if (OF32) {
                float* c0 = Cf + (long long)bz * sC + (long long)mr * ldc + nc;
                float* c1 = Cf + (long long)bz * sC + (long long)(mr + 8) * ldc + nc;
                *(float2*)c0 = make_float2(v00, v01);
                *(float2*)c1 = make_float2(v10, v11);
            }
            if (OSPLIT) {
                long long o0 = (long long)bz * sCh + (long long)mr * ldc + nc;
                long long o1 = (long long)bz * sCh + (long long)(mr + 8) * ldc + nc;
                if (Cl) {
                    __half h00, l00, h01, l01, h10, l10, h11, l11;
                    split2(v00, h00, l00); split2(v01, h01, l01);
                    split2(v10, h10, l10); split2(v11, h11, l11);
                    *(__half2*)&Ch[o0] = __halves2half2(h00, h01);
                    *(__half2*)&Cl[o0] = __halves2half2(l00, l01);
                    *(__half2*)&Ch[o1] = __halves2half2(h10, h11);
                    *(__half2*)&Cl[o1] = __halves2half2(l10, l11);
                } else {
                    *(__half2*)&Ch[o0] = __halves2half2(__float2half_rn(v00),
                                                        __float2half_rn(v01));
                    *(__half2*)&Ch[o1] = __halves2half2(__float2half_rn(v10),
                                                        __float2half_rn(v11));
                }
            }
        }
    }
}

// ---------------- fused softmax(-E) rows of 512 + split ----------------
__global__ void softmax_neg512_split_k(const float* __restrict__ e,
                                       __half* __restrict__ oh,
                                       __half* __restrict__ ol, int nrows) {
    int row  = blockIdx.x * 8 + (threadIdx.x >> 5);
    int lane = threadIdx.x & 31;
    if (row >= nrows) return;
    const float* p = e + (long long)row * CC + lane * 16;
    float v[16];
    float mx = -3.4e38f;
    #pragma unroll
    for (int q = 0; q < 4; ++q) {
        float4 f = *(const float4*)(p + 4 * q);
        v[4 * q + 0] = -f.x; v[4 * q + 1] = -f.y;
        v[4 * q + 2] = -f.z; v[4 * q + 3] = -f.w;
    }
    #pragma unroll
    for (int j = 0; j < 16; ++j) mx = fmaxf(mx, v[j]);
    #pragma unroll
    for (int o = 16; o; o >>= 1) mx = fmaxf(mx, __shfl_xor_sync(0xffffffffu, mx, o));
    float s = 0.f;
    #pragma unroll
    for (int j = 0; j < 16; ++j) { v[j] = __expf(v[j] - mx); s += v[j]; }
    #pragma unroll
    for (int o = 16; o; o >>= 1) s += __shfl_xor_sync(0xffffffffu, s, o);
    float inv = 1.f / s;
    long long off = (long long)row * CC + lane * 16;
    #pragma unroll
    for (int j = 0; j < 16; j += 2) {
        __half h0, l0, h1, l1;
        split2(v[j] * inv, h0, l0);
        split2(v[j + 1] * inv, h1, l1);
        *(__half2*)&oh[off + j] = __halves2half2(h0, h1);
        *(__half2*)&ol[off + j] = __halves2half2(l0, l1);
    }
}

// ---------------- fused softmax rows of 2304 -> fp16 (hi only) ----------------
__global__ void __launch_bounds__(256)
softmax2304_h_k(const float* __restrict__ e, __half* __restrict__ oh) {
    __shared__ float redm[8];
    __shared__ float reds[8];
    int tn = threadIdx.x;
    const float* p = e + (size_t)blockIdx.x * HW;
    float v[9];
    float mx = -3.4e38f;
    #pragma unroll
    for (int j = 0; j < 9; ++j) {
        v[j] = p[tn + 256 * j];
        mx = fmaxf(mx, v[j]);
    }
    #pragma unroll
    for (int o = 16; o; o >>= 1) mx = fmaxf(mx, __shfl_xor_sync(0xffffffffu, mx, o));
    if ((tn & 31) == 0) redm[tn >> 5] = mx;
    __syncthreads();
    mx = redm[0];
    #pragma unroll
    for (int i = 1; i < 8; ++i) mx = fmaxf(mx, redm[i]);
    float s = 0.f;
    #pragma unroll
    for (int j = 0; j < 9; ++j) { v[j] = __expf(v[j] - mx); s += v[j]; }
    #pragma unroll
    for (int o = 16; o; o >>= 1) s += __shfl_xor_sync(0xffffffffu, s, o);
    if ((tn & 31) == 0) reds[tn >> 5] = s;
    __syncthreads();
    s = reds[0];
    #pragma unroll
    for (int i = 1; i < 8; ++i) s += reds[i];
    float inv = 1.f / s;
    size_t off = (size_t)blockIdx.x * HW + tn;
    #pragma unroll
    for (int j = 0; j < 9; ++j)
        oh[off + 256 * j] = __float2half_rn(v[j] * inv);
}

// ---------------- launch ----------------
extern "C" void kernel_launch(void* const* d_in, const int* in_sizes, int n_in,
                              void* d_out, int out_size) {
    const float* x   = (const float*)d_in[0];
    const float* Wqc = (const float*)d_in[1];
    const float* bqc = (const float*)d_in[2];
    const float* Wkc = (const float*)d_in[3];
    const float* bkc = (const float*)d_in[4];
    const float* Wqp = (const float*)d_in[5];
    const float* bqp = (const float*)d_in[6];
    const float* Wkp = (const float*)d_in[7];
    const float* bkp = (const float*)d_in[8];

    float* out   = (float*)d_out;
    float* out_c = out;                              // (B, 2C, HW)
    float* out_p = out + (size_t)BB * OCQ * HW;      // (B, 2C, H, W)

    __half *col_h, *col_l, *wq_h, *wq_l, *wp_h, *wp_l, *qk_h, *qk_l;
    __half *ac_h, *ac_l, *xt_h, *xt_l, *oc_h, *qpt_h, *qpt_l, *kpt_h, *kpt_l, *ap_h;
    float *bias, *bias2, *attn_c, *qpkp, *attn_p;
    cudaGetSymbolAddress((void**)&col_h, g_col_h);
    cudaGetSymbolAddress((void**)&col_l, g_col_l);
    cudaGetSymbolAddress((void**)&wq_h,  g_wq_h);
    cudaGetSymbolAddress((void**)&wq_l,  g_wq_l);
    cudaGetSymbolAddress((void**)&wp_h,  g_wp_h);
    cudaGetSymbolAddress((void**)&wp_l,  g_wp_l);
    cudaGetSymbolAddress((void**)&bias,  g_bias);
    cudaGetSymbolAddress((void**)&bias2, g_bias2);
    cudaGetSymbolAddress((void**)&qk_h,  g_qk_h);
    cudaGetSymbolAddress((void**)&qk_l,  g_qk_l);
    cudaGetSymbolAddress((void**)&attn_c, g_attn_c);
    cudaGetSymbolAddress((void**)&ac_h,  g_ac_h);
    cudaGetSymbolAddress((void**)&ac_l,  g_ac_l);
    cudaGetSymbolAddress((void**)&xt_h,  g_xt_h);
    cudaGetSymbolAddress((void**)&xt_l,  g_xt_l);
    cudaGetSymbolAddress((void**)&oc_h,  g_oc_h);
    cudaGetSymbolAddress((void**)&qpkp,  g_qpkp);
    cudaGetSymbolAddress((void**)&qpt_h, g_qpt_h);
    cudaGetSymbolAddress((void**)&qpt_l, g_qpt_l);
    cudaGetSymbolAddress((void**)&kpt_h, g_kpt_h);
    cudaGetSymbolAddress((void**)&kpt_l, g_kpt_l);
    cudaGetSymbolAddress((void**)&attn_p, g_attn_p);
    cudaGetSymbolAddress((void**)&ap_h,  g_ap_h);

    const int SM3 = 2 * 4 * 128 * 40 * 2;   // 81920 B (TERMS=3)
    const int SM1 = 2 * 2 * 128 * 40 * 2;   // 40960 B (TERMS=1)
    cudaFuncSetAttribute(gemm_fp16<3, false, true>,
                         cudaFuncAttributeMaxDynamicSharedMemorySize, SM3);
    cudaFuncSetAttribute(gemm_fp16<3, true, false>,
                         cudaFuncAttributeMaxDynamicSharedMemorySize, SM3);
    cudaFuncSetAttribute(gemm_fp16<3, true, true>,
                         cudaFuncAttributeMaxDynamicSharedMemorySize, SM3);
    cudaFuncSetAttribute(gemm_fp16<1, true, false>,
                         cudaFuncAttributeMaxDynamicSharedMemorySize, SM1);

    // --- prep: weight/bias splits, im2col, x transpose ---
    split_f32_k<<<((long long)OCQ * KCV + 255) / 256, 256>>>(Wqc, wq_h, wq_l,
                                                             (long long)OCQ * KCV);
    split_f32_k<<<((long long)CC * KCV + 255) / 256, 256>>>(
        Wkc, wq_h + (size_t)OCQ * KCV, wq_l + (size_t)OCQ * KCV,
        (long long)CC * KCV);
    split_f32_k<<<(DD * CC + 255) / 256, 256>>>(Wqp, wp_h, wp_l, DD * CC);
    split_f32_k<<<(DD * CC + 255) / 256, 256>>>(
        Wkp, wp_h + (size_t)DD * CC, wp_l + (size_t)DD * CC, DD * CC);
    concat_bias_k<<<(MQK + 255) / 256, 256>>>(bqc, bkc, bias, OCQ, MQK);
    concat_bias_k<<<1, 128, 0>>>(bqp, bkp, bias2, DD, DD2);
    im2col_split_k<<<dim3((HWS * (KCV / 4) + 255) / 256, BB), 256>>>(x);
    transpose_split_k<<<dim3(HW / 32, CC / 32, BB), dim3(32, 8)>>>(
        x, xt_h, xt_l, CC, HW, (long long)CC * HW, (long long)CC * HW);

    // --- combined conv: qckc[1536,640] = W @ col + bias -> split (ldc=HWSP) ---
    gemm_fp16<3, false, true><<<dim3(HWSP / 128, MQK / 128, BB), 256, SM3>>>(
        MQK, HWSP, KCV, wq_h, wq_l, KCV, 0LL,
        col_h, col_l, KCV, (long long)HWSP * KCV,
        nullptr, HWSP, 0LL, qk_h, qk_l, (long long)MQK * HWSP, bias);

    // --- energy = qc @ kc^T (M=1024,N=512,K=576) -> fp32 ---
    gemm_fp16<3, true, false><<<dim3(CC / 128, OCQ / 128, BB), 256, SM3>>>(
        OCQ, CC, HWS,
        qk_h, qk_l, HWSP, (long long)MQK * HWSP,
        qk_h + (size_t)OCQ * HWSP, qk_l + (size_t)OCQ * HWSP, HWSP,
        (long long)MQK * HWSP,
        attn_c, CC, (long long)OCQ * CC, nullptr, nullptr, 0LL, nullptr);

    // --- fused softmax(-energy) + split ---
    softmax_neg512_split_k<<<(BB * OCQ) / 8, 256>>>(attn_c, ac_h, ac_l, BB * OCQ);

    // --- out_c = attn_c @ xf (M=1024,N=2304,K=512) -> fp32 (d_out) + hi fp16 ---
    gemm_fp16<3, true, true><<<dim3(HW / 128, OCQ / 128, BB), 256, SM3>>>(
        OCQ, HW, CC, ac_h, ac_l, CC, (long long)OCQ * CC,
        xt_h, xt_l, CC, (long long)HW * CC,
        out_c, HW, (long long)OCQ * HW,
        oc_h, nullptr, (long long)OCQ * HW, nullptr);

    // --- qp+kp combined: [128,2304] = Wp @ xf + bias2 ---
    gemm_fp16<3, true, false><<<dim3(HW / 128, DD2 / 128, BB), 256, SM3>>>(
        DD2, HW, CC, wp_h, wp_l, CC, 0LL,
        xt_h, xt_l, CC, (long long)HW * CC,
        qpkp, HW, (long long)DD2 * HW, nullptr, nullptr, 0LL, bias2);

    // --- transpose-split qp (rows 0..63) and kp (rows 64..127) ---
    transpose_split_k<<<dim3(HW / 32, DD / 32, BB), dim3(32, 8)>>>(
        qpkp, qpt_h, qpt_l, DD, HW, (long long)DD2 * HW, (long long)HW * DD);
    transpose_split_k<<<dim3(HW / 32, DD / 32, BB), dim3(32, 8)>>>(
        qpkp + (size_t)DD * HW, kpt_h, kpt_l, DD, HW,
        (long long)DD2 * HW, (long long)HW * DD);

    // --- energy_p = qp^T @ kp (M=N=2304, K=64) -> fp32 ---
    gemm_fp16<3, true, false><<<dim3(HW / 128, HW / 128, BB), 256, SM3>>>(
        HW, HW, DD, qpt_h, qpt_l, DD, (long long)HW * DD,
        kpt_h, kpt_l, DD, (long long)HW * DD,
        attn_p, HW, (long long)HW * HW, nullptr, nullptr, 0LL, nullptr);

    // --- fused softmax rows of 2304 -> fp16 hi ---
    softmax2304_h_k<<<BB * HW, 256>>>(attn_p, ap_h);

    // --- out_p = out_c @ attn_p^T (M=1024,N=2304,K=2304), 1-term -> fp32 ---
    gemm_fp16<1, true, false><<<dim3(HW / 128, OCQ / 128, BB), 256, SM1>>>(
        OCQ, HW, HW, oc_h, nullptr, HW, (long long)OCQ * HW,
        ap_h, nullptr, HW, (long long)HW * HW,
        out_p, HW, (long long)OCQ * HW, nullptr, nullptr, 0LL, nullptr);
}

// round 12
// speedup vs baseline: 1.1422x; 1.1422x over previous
#include <cuda_runtime.h>
#include <cuda_fp16.h>
#include <cstdint>
#include <cstddef>

// ---------------- problem constants ----------------
#define BB   8
#define CC   512
#define HH   48
#define HW   2304     // 48*48
#define HOS  24       // stride-2 output spatial
#define HWS  576      // 24*24
#define HWSP 640      // padded N for 128-tiles
#define KCV  4608     // 512*9 (im2col K)
#define OCQ  1024     // 2C
#define MQK  1536     // combined conv output rows (2C + C)
#define DD   64       // C/8
#define DD2  128      // combined qp+kp rows

// ---------------- scratch (device globals; allocation-free) ----------------
__device__ __align__(128) __half g_col_h[(size_t)BB * HWSP * KCV];
__device__ __align__(128) __half g_col_l[(size_t)BB * HWSP * KCV];
__device__ __align__(128) __half g_wq_h[(size_t)MQK * KCV];
__device__ __align__(128) __half g_wq_l[(size_t)MQK * KCV];
__device__ float  g_bias[MQK];
__device__ __align__(128) __half g_wp_h[(size_t)DD2 * CC];
__device__ __align__(128) __half g_wp_l[(size_t)DD2 * CC];
__device__ float  g_bias2[DD2];
__device__ __align__(128) __half g_qk_h[(size_t)BB * MQK * HWSP];
__device__ __align__(128) __half g_qk_l[(size_t)BB * MQK * HWSP];
__device__ __align__(128) float  g_attn_c[(size_t)BB * OCQ * CC];   // energies
__device__ __align__(128) __half g_ac_h[(size_t)BB * OCQ * CC];
__device__ __align__(128) __half g_ac_l[(size_t)BB * OCQ * CC];
__device__ __align__(128) __half g_xt_h[(size_t)BB * HW * CC];
__device__ __align__(128) __half g_xt_l[(size_t)BB * HW * CC];
__device__ __align__(128) __half g_oc_h[(size_t)BB * OCQ * HW];
__device__ __align__(128) float  g_qpkp[(size_t)BB * DD2 * HW];
__device__ __align__(128) __half g_qpt_h[(size_t)BB * HW * DD];
__device__ __align__(128) __half g_qpt_l[(size_t)BB * HW * DD];
__device__ __align__(128) __half g_kpt_h[(size_t)BB * HW * DD];
__device__ __align__(128) __half g_kpt_l[(size_t)BB * HW * DD];
__device__ __align__(128) float  g_attn_p[(size_t)BB * HW * HW];    // energies
__device__ __align__(128) __half g_ap_h[(size_t)BB * HW * HW];

// ---------------- helpers ----------------
__device__ __forceinline__ void split2(float v, __half& h, __half& l) {
    h = __float2half_rn(v);
    l = __float2half_rn(v - __half2float(h));
}
__device__ __forceinline__ void mma16816(float* c, const uint32_t* a,
                                         uint32_t b0, uint32_t b1) {
    asm volatile(
        "mma.sync.aligned.m16n8k16.row.col.f32.f16.f16.f32 "
        "{%0,%1,%2,%3},{%4,%5,%6,%7},{%8,%9},{%0,%1,%2,%3};"
        : "+f"(c[0]), "+f"(c[1]), "+f"(c[2]), "+f"(c[3])
        : "r"(a[0]), "r"(a[1]), "r"(a[2]), "r"(a[3]), "r"(b0), "r"(b1));
}
__device__ __forceinline__ void ldsm4(uint32_t* r, uint32_t addr) {
    asm volatile("ldmatrix.sync.aligned.m8n8.x4.shared.b16 {%0,%1,%2,%3}, [%4];"
        : "=r"(r[0]), "=r"(r[1]), "=r"(r[2]), "=r"(r[3]) : "r"(addr));
}
#define CP16(dst_u32, src_ptr) \
    asm volatile("cp.async.cg.shared.global [%0], [%1], 16;" :: "r"(dst_u32), "l"(src_ptr))
#define CP_COMMIT() asm volatile("cp.async.commit_group;" ::: "memory")

// ---------------- im2col (3x3 s2 p1) -> split fp16, [b][p][k], 4 k/thread ----------------
__global__ void im2col_split_k(const float* __restrict__ x) {
    const int KQ = KCV / 4;                       // 1152
    int idx = blockIdx.x * blockDim.x + threadIdx.x;
    int b = blockIdx.y;
    if (idx >= HWS * KQ) return;
    int p  = idx / KQ;
    int k0 = (idx - p * KQ) * 4;
    int oy = p / HOS, ox = p - oy * HOS;
    int iy0 = 2 * oy - 1, ix0 = 2 * ox - 1;
    const float* xb = x + (size_t)b * CC * HW;
    __half h[4], l[4];
    #pragma unroll
    for (int j = 0; j < 4; ++j) {
        int k = k0 + j;
        int ic = k / 9;
        int r  = k - ic * 9;
        int ky = r / 3, kx = r - ky * 3;
        int iy = iy0 + ky, ix = ix0 + kx;
        float v = 0.f;
        if ((unsigned)iy < (unsigned)HH && (unsigned)ix < (unsigned)HH)
            v = xb[((size_t)ic * HH + iy) * HH + ix];
        split2(v, h[j], l[j]);
    }
    size_t d = ((size_t)b * HWSP + p) * KCV + k0;
    *(__half2*)&g_col_h[d]     = __halves2half2(h[0], h[1]);
    *(__half2*)&g_col_h[d + 2] = __halves2half2(h[2], h[3]);
    *(__half2*)&g_col_l[d]     = __halves2half2(l[0], l[1]);
    *(__half2*)&g_col_l[d + 2] = __halves2half2(l[2], l[3]);
}

// ---------------- elementwise fp32 -> (hi, lo) fp16 (weights) ----------------
__global__ void split_f32_k(const float* __restrict__ s, __half* __restrict__ h,
                            __half* __restrict__ l, long long n) {
    long long i = (long long)blockIdx.x * blockDim.x + threadIdx.x;
    if (i >= n) return;
    __half hh, ll; split2(s[i], hh, ll);
    h[i] = hh; l[i] = ll;
}
__global__ void concat_bias_k(const float* a, const float* b, float* dst,
                              int na, int ntot) {
    int i = blockIdx.x * blockDim.x + threadIdx.x;
    if (i < na) dst[i] = a[i];
    else if (i < ntot) dst[i] = b[i - na];
}

// ---------------- tiled transpose + split: [R][Cn] fp32 -> [Cn][R] hi/lo ----------------
__global__ void transpose_split_k(const float* __restrict__ src,
                                  __half* __restrict__ oh, __half* __restrict__ ol,
                                  int R, int Cn, long long sIn, long long sOut) {
    __shared__ float tile[32][33];
    int b = blockIdx.z;
    src += (long long)b * sIn;
    oh  += (long long)b * sOut;
    ol  += (long long)b * sOut;
    int c0 = blockIdx.x * 32;
    int r0 = blockIdx.y * 32;
    int tx = threadIdx.x, ty = threadIdx.y;
    #pragma unroll
    for (int i = 0; i < 4; ++i)
        tile[ty + 8 * i][tx] = src[(long long)(r0 + ty + 8 * i) * Cn + c0 + tx];
    __syncthreads();
    #pragma unroll
    for (int i = 0; i < 4; ++i) {
        float v = tile[tx][ty + 8 * i];
        __half h, l; split2(v, h, l);
        long long o = (long long)(c0 + ty + 8 * i) * R + r0 + tx;
        oh[o] = h; ol[o] = l;
    }
}

// ---------------- split-fp16 tensor-core GEMM (ldmatrix, 4 warps — R8 proven) ----------------
// C = op(A)@op(B), A,B pre-split hi/lo fp16, stored [rows][K] K-contig.
// TERMS 3: AhBh+AlBh+AhBl ; 2: AhBh+AlBh ; 1: AhBh.
// Tile 128x128, BK=32, 128 threads, m16n8k16.
template <int TERMS, bool OF32, bool OSPLIT>
__global__ void __launch_bounds__(128, 2)
gemm_fp16(int M, int N, int K,
          const __half* __restrict__ Ah, const __half* __restrict__ Al,
          int lda, long long sA,
          const __half* __restrict__ Bh, const __half* __restrict__ Bl,
          int ldb, long long sB,
          float* __restrict__ Cf, int ldc, long long sC,
          __half* __restrict__ Ch, __half* __restrict__ Cl, long long sCh,
          const float* __restrict__ bias)
{
    constexpr int NA = (TERMS >= 2) ? 2 : 1;            // A comps
    constexpr int NB = (TERMS >= 3) ? 2 : 1;            // B comps
    constexpr int NCOMP = NA + NB;
    constexpr int MSZ = 128 * 40;                       // halves per component
    constexpr int SS  = NCOMP * MSZ;                    // halves per stage
    extern __shared__ __half sm[];

    int bz = blockIdx.z;
    Ah += (long long)bz * sA;
    if (TERMS >= 2) Al += (long long)bz * sA;
    Bh += (long long)bz * sB;
    if (TERMS >= 3) Bl += (long long)bz * sB;

    int m0 = blockIdx.y * 128;
    int n0 = blockIdx.x * 128;
    int tid  = threadIdx.x;
    int lane = tid & 31;
    int warp = tid >> 5;
    int wm = (warp >> 1) * 64;
    int wn = (warp & 1) * 64;
    int g = lane >> 2;
    int t = lane & 3;

    uint32_t smbase = (uint32_t)__cvta_generic_to_shared(sm);
    uint32_t a_loff = (uint32_t)(((lane & 7) + ((lane >> 3) & 1) * 8) * 40
                                 + (lane >> 4) * 8);
    uint32_t b_loff = (uint32_t)(((lane & 7) + (lane >> 4) * 8) * 40
                                 + ((lane >> 3) & 1) * 8);

    auto issue = [&](int stage, int k0) {
        #pragma unroll
        for (int j = 0; j < NCOMP * 4; ++j) {
            int q = j * 128 + tid;
            int comp = q >> 9;           // 512 16B-chunks per component
            int w = q & 511;
            int row = w >> 2, seg = w & 3;
            const __half* base;
            int ld, r0;
            if (comp < NA) { ld = lda; r0 = m0; base = (comp == 0) ? Ah : Al; }
            else           { ld = ldb; r0 = n0; base = (comp == NA) ? Bh : Bl; }
            const __half* src = base + (long long)(r0 + row) * ld + k0 + seg * 8;
            uint32_t dst = smbase +
                (uint32_t)(stage * SS + comp * MSZ + row * 40 + seg * 8) * 2;
            CP16(dst, src);
        }
    };

    float acc[4][8][4] = {};
    int nk = K / 32;

    issue(0, 0);
    CP_COMMIT();
    if (nk > 1) issue(1, 32);
    CP_COMMIT();

    for (int i = 0; i < nk; ++i) {
        if (i < nk - 1) asm volatile("cp.async.wait_group 1;" ::: "memory");
        else            asm volatile("cp.async.wait_group 0;" ::: "memory");
        __syncthreads();

        uint32_t st  = smbase + (uint32_t)((i & 1) * SS) * 2;
        uint32_t pAh = st;
        uint32_t pAl = st + (uint32_t)MSZ * 2;              // valid if NA==2
        uint32_t pBh = st + (uint32_t)(NA * MSZ) * 2;
        uint32_t pBl = st + (uint32_t)((NA + 1) * MSZ) * 2; // valid if NB==2

        #pragma unroll
        for (int kk = 0; kk < 32; kk += 16) {
            uint32_t ah[4][4], al[4][4];
            #pragma unroll
            for (int im = 0; im < 4; ++im) {
                uint32_t ro = (uint32_t)((wm + im * 16) * 40 + kk);
                ldsm4(ah[im], pAh + (ro + a_loff) * 2);
                if (TERMS >= 2) ldsm4(al[im], pAl + (ro + a_loff) * 2);
            }
            #pragma unroll
            for (int jp = 0; jp < 4; ++jp) {
                uint32_t co = (uint32_t)((wn + jp * 16) * 40 + kk);
                uint32_t bh[4], bl[4];
                ldsm4(bh, pBh + (co + b_loff) * 2);
                if (TERMS >= 3) ldsm4(bl, pBl + (co + b_loff) * 2);
                #pragma unroll
                for (int im = 0; im < 4; ++im) {
                    mma16816(acc[im][2 * jp],     ah[im], bh[0], bh[1]);
                    mma16816(acc[im][2 * jp + 1], ah[im], bh[2], bh[3]);
                    if (TERMS >= 2) {
                        mma16816(acc[im][2 * jp],     al[im], bh[0], bh[1]);
                        mma16816(acc[im][2 * jp + 1], al[im], bh[2], bh[3]);
                    }
                    if (TERMS >= 3) {
                        mma16816(acc[im][2 * jp],     ah[im], bl[0], bl[1]);
                        mma16816(acc[im][2 * jp + 1], ah[im], bl[2], bl[3]);
                    }
                }
            }
        }
        __syncthreads();
        if (i + 2 < nk) {
            issue((i + 2) & 1, (i + 2) * 32);
            CP_COMMIT();
        }
    }

    // ---------------- epilogue ----------------
    #pragma unroll
    for (int im = 0; im < 4; ++im) {
        int mr = m0 + wm + im * 16 + g;
        float bi0 = bias ? bias[mr] : 0.f;
        float bi1 = bias ? bias[mr + 8] : 0.f;
        #pragma unroll
        for (int jn = 0; jn < 8; ++jn) {
            int nc = n0 + wn + jn * 8 + 2 * t;
            float v00 = acc[im][jn][0] + bi0, v01 = acc[im][jn][1] + bi0;
            float v10 = acc[im][jn][2] + bi1, v11 = acc[im][jn][3] + bi1;
            if (OF32) {
                float* c0 = Cf + (long long)bz * sC + (long long)mr * ldc + nc;
                float* c1 = Cf + (long long)bz * sC + (long long)(mr + 8) * ldc + nc;
                *(float2*)c0 = make_float2(v00, v01);
                *(float2*)c1 = make_float2(v10, v11);
            }
            if (OSPLIT) {
                long long o0 = (long long)bz * sCh + (long long)mr * ldc + nc;
                long long o1 = (long long)bz * sCh + (long long)(mr + 8) * ldc + nc;
                if (Cl) {
                    __half h00, l00, h01, l01, h10, l10, h11, l11;
                    split2(v00, h00, l00); split2(v01, h01, l01);
                    split2(v10, h10, l10); split2(v11, h11, l11);
                    *(__half2*)&Ch[o0] = __halves2half2(h00, h01);
                    *(__half2*)&Cl[o0] = __halves2half2(l00, l01);
                    *(__half2*)&Ch[o1] = __halves2half2(h10, h11);
                    *(__half2*)&Cl[o1] = __halves2half2(l10, l11);
                } else {
                    *(__half2*)&Ch[o0] = __halves2half2(__float2half_rn(v00),
                                                        __float2half_rn(v01));
                    *(__half2*)&Ch[o1] = __halves2half2(__float2half_rn(v10),
                                                        __float2half_rn(v11));
                }
            }
        }
    }
}

// ---------------- fused softmax(-E) rows of 512 + split ----------------
__global__ void softmax_neg512_split_k(const float* __restrict__ e,
                                       __half* __restrict__ oh,
                                       __half* __restrict__ ol, int nrows) {
    int row  = blockIdx.x * 8 + (threadIdx.x >> 5);
    int lane = threadIdx.x & 31;
    if (row >= nrows) return;
    const float* p = e + (long long)row * CC + lane * 16;
    float v[16];
    float mx = -3.4e38f;
    #pragma unroll
    for (int q = 0; q < 4; ++q) {
        float4 f = *(const float4*)(p + 4 * q);
        v[4 * q + 0] = -f.x; v[4 * q + 1] = -f.y;
        v[4 * q + 2] = -f.z; v[4 * q + 3] = -f.w;
    }
    #pragma unroll
    for (int j = 0; j < 16; ++j) mx = fmaxf(mx, v[j]);
    #pragma unroll
    for (int o = 16; o; o >>= 1) mx = fmaxf(mx, __shfl_xor_sync(0xffffffffu, mx, o));
    float s = 0.f;
    #pragma unroll
    for (int j = 0; j < 16; ++j) { v[j] = __expf(v[j] - mx); s += v[j]; }
    #pragma unroll
    for (int o = 16; o; o >>= 1) s += __shfl_xor_sync(0xffffffffu, s, o);
    float inv = 1.f / s;
    long long off = (long long)row * CC + lane * 16;
    #pragma unroll
    for (int j = 0; j < 16; j += 2) {
        __half h0, l0, h1, l1;
        split2(v[j] * inv, h0, l0);
        split2(v[j + 1] * inv, h1, l1);
        *(__half2*)&oh[off + j] = __halves2half2(h0, h1);
        *(__half2*)&ol[off + j] = __halves2half2(l0, l1);
    }
}

// ---------------- fused softmax rows of 2304 -> fp16 (hi only) ----------------
__global__ void __launch_bounds__(256)
softmax2304_h_k(const float* __restrict__ e, __half* __restrict__ oh) {
    __shared__ float redm[8];
    __shared__ float reds[8];
    int tn = threadIdx.x;
    const float* p = e + (size_t)blockIdx.x * HW;
    float v[9];
    float mx = -3.4e38f;
    #pragma unroll
    for (int j = 0; j < 9; ++j) {
        v[j] = p[tn + 256 * j];
        mx = fmaxf(mx, v[j]);
    }
    #pragma unroll
    for (int o = 16; o; o >>= 1) mx = fmaxf(mx, __shfl_xor_sync(0xffffffffu, mx, o));
    if ((tn & 31) == 0) redm[tn >> 5] = mx;
    __syncthreads();
    mx = redm[0];
    #pragma unroll
    for (int i = 1; i < 8; ++i) mx = fmaxf(mx, redm[i]);
    float s = 0.f;
    #pragma unroll
    for (int j = 0; j < 9; ++j) { v[j] = __expf(v[j] - mx); s += v[j]; }
    #pragma unroll
    for (int o = 16; o; o >>= 1) s += __shfl_xor_sync(0xffffffffu, s, o);
    if ((tn & 31) == 0) reds[tn >> 5] = s;
    __syncthreads();
    s = reds[0];
    #pragma unroll
    for (int i = 1; i < 8; ++i) s += reds[i];
    float inv = 1.f / s;
    size_t off = (size_t)blockIdx.x * HW + tn;
    #pragma unroll
    for (int j = 0; j < 9; ++j)
        oh[off + 256 * j] = __float2half_rn(v[j] * inv);
}

// ---------------- launch ----------------
extern "C" void kernel_launch(void* const* d_in, const int* in_sizes, int n_in,
                              void* d_out, int out_size) {
    const float* x   = (const float*)d_in[0];
    const float* Wqc = (const float*)d_in[1];
    const float* bqc = (const float*)d_in[2];
    const float* Wkc = (const float*)d_in[3];
    const float* bkc = (const float*)d_in[4];
    const float* Wqp = (const float*)d_in[5];
    const float* bqp = (const float*)d_in[6];
    const float* Wkp = (const float*)d_in[7];
    const float* bkp = (const float*)d_in[8];

    float* out   = (float*)d_out;
    float* out_c = out;                              // (B, 2C, HW)
    float* out_p = out + (size_t)BB * OCQ * HW;      // (B, 2C, H, W)

    __half *col_h, *col_l, *wq_h, *wq_l, *wp_h, *wp_l, *qk_h, *qk_l;
    __half *ac_h, *ac_l, *xt_h, *xt_l, *oc_h, *qpt_h, *qpt_l, *kpt_h, *kpt_l, *ap_h;
    float *bias, *bias2, *attn_c, *qpkp, *attn_p;
    cudaGetSymbolAddress((void**)&col_h, g_col_h);
    cudaGetSymbolAddress((void**)&col_l, g_col_l);
    cudaGetSymbolAddress((void**)&wq_h,  g_wq_h);
    cudaGetSymbolAddress((void**)&wq_l,  g_wq_l);
    cudaGetSymbolAddress((void**)&wp_h,  g_wp_h);
    cudaGetSymbolAddress((void**)&wp_l,  g_wp_l);
    cudaGetSymbolAddress((void**)&bias,  g_bias);
    cudaGetSymbolAddress((void**)&bias2, g_bias2);
    cudaGetSymbolAddress((void**)&qk_h,  g_qk_h);
    cudaGetSymbolAddress((void**)&qk_l,  g_qk_l);
    cudaGetSymbolAddress((void**)&attn_c, g_attn_c);
    cudaGetSymbolAddress((void**)&ac_h,  g_ac_h);
    cudaGetSymbolAddress((void**)&ac_l,  g_ac_l);
    cudaGetSymbolAddress((void**)&xt_h,  g_xt_h);
    cudaGetSymbolAddress((void**)&xt_l,  g_xt_l);
    cudaGetSymbolAddress((void**)&oc_h,  g_oc_h);
    cudaGetSymbolAddress((void**)&qpkp,  g_qpkp);
    cudaGetSymbolAddress((void**)&qpt_h, g_qpt_h);
    cudaGetSymbolAddress((void**)&qpt_l, g_qpt_l);
    cudaGetSymbolAddress((void**)&kpt_h, g_kpt_h);
    cudaGetSymbolAddress((void**)&kpt_l, g_kpt_l);
    cudaGetSymbolAddress((void**)&attn_p, g_attn_p);
    cudaGetSymbolAddress((void**)&ap_h,  g_ap_h);

    const int SM3 = 2 * 4 * 128 * 40 * 2;   // 81920 B (TERMS=3)
    const int SM1 = 2 * 2 * 128 * 40 * 2;   // 40960 B (TERMS=1)
    cudaFuncSetAttribute(gemm_fp16<3, false, true>,
                         cudaFuncAttributeMaxDynamicSharedMemorySize, SM3);
    cudaFuncSetAttribute(gemm_fp16<3, true, false>,
                         cudaFuncAttributeMaxDynamicSharedMemorySize, SM3);
    cudaFuncSetAttribute(gemm_fp16<3, true, true>,
                         cudaFuncAttributeMaxDynamicSharedMemorySize, SM3);
    cudaFuncSetAttribute(gemm_fp16<1, true, false>,
                         cudaFuncAttributeMaxDynamicSharedMemorySize, SM1);

    // --- one-time stream/event infra (host-side, no device allocation) ---
    static cudaStream_t s2 = nullptr;
    static cudaEvent_t evStart = nullptr, evXt = nullptr, evPam = nullptr;
    if (!s2) {
        cudaStreamCreateWithFlags(&s2, cudaStreamNonBlocking);
        cudaEventCreateWithFlags(&evStart, cudaEventDisableTiming);
        cudaEventCreateWithFlags(&evXt,    cudaEventDisableTiming);
        cudaEventCreateWithFlags(&evPam,   cudaEventDisableTiming);
    }
    cudaStream_t s1 = 0;   // default stream (captured by harness)

    // ===== fork: s2 joins the capture via evStart =====
    cudaEventRecord(evStart, s1);
    cudaStreamWaitEvent(s2, evStart, 0);

    // --- s1: CAM-side prep ---
    split_f32_k<<<((long long)OCQ * KCV + 255) / 256, 256, 0, s1>>>(
        Wqc, wq_h, wq_l, (long long)OCQ * KCV);
    split_f32_k<<<((long long)CC * KCV + 255) / 256, 256, 0, s1>>>(
        Wkc, wq_h + (size_t)OCQ * KCV, wq_l + (size_t)OCQ * KCV,
        (long long)CC * KCV);
    concat_bias_k<<<(MQK + 255) / 256, 256, 0, s1>>>(bqc, bkc, bias, OCQ, MQK);
    im2col_split_k<<<dim3((HWS * (KCV / 4) + 255) / 256, BB), 256, 0, s1>>>(x);
    transpose_split_k<<<dim3(HW / 32, CC / 32, BB), dim3(32, 8), 0, s1>>>(
        x, xt_h, xt_l, CC, HW, (long long)CC * HW, (long long)CC * HW);
    cudaEventRecord(evXt, s1);                 // xt ready for PAM

    // --- s2: PAM-side prep (independent of s1 work) ---
    split_f32_k<<<(DD * CC + 255) / 256, 256, 0, s2>>>(Wqp, wp_h, wp_l, DD * CC);
    split_f32_k<<<(DD * CC + 255) / 256, 256, 0, s2>>>(
        Wkp, wp_h + (size_t)DD * CC, wp_l + (size_t)DD * CC, DD * CC);
    concat_bias_k<<<1, 128, 0, s2>>>(bqp, bkp, bias2, DD, DD2);

    // --- s1: CAM chain ---
    gemm_fp16<3, false, true><<<dim3(HWSP / 128, MQK / 128, BB), 128, SM3, s1>>>(
        MQK, HWSP, KCV, wq_h, wq_l, KCV, 0LL,
        col_h, col_l, KCV, (long long)HWSP * KCV,
        nullptr, HWSP, 0LL, qk_h, qk_l, (long long)MQK * HWSP, bias);
    gemm_fp16<3, true, false><<<dim3(CC / 128, OCQ / 128, BB), 128, SM3, s1>>>(
        OCQ, CC, HWS,
        qk_h, qk_l, HWSP, (long long)MQK * HWSP,
        qk_h + (size_t)OCQ * HWSP, qk_l + (size_t)OCQ * HWSP, HWSP,
        (long long)MQK * HWSP,
        attn_c, CC, (long long)OCQ * CC, nullptr, nullptr, 0LL, nullptr);
    softmax_neg512_split_k<<<(BB * OCQ) / 8, 256, 0, s1>>>(attn_c, ac_h, ac_l,
                                                           BB * OCQ);
    gemm_fp16<3, true, true><<<dim3(HW / 128, OCQ / 128, BB), 128, SM3, s1>>>(
        OCQ, HW, CC, ac_h, ac_l, CC, (long long)OCQ * CC,
        xt_h, xt_l, CC, (long long)HW * CC,
        out_c, HW, (long long)OCQ * HW,
        oc_h, nullptr, (long long)OCQ * HW, nullptr);

    // --- s2: PAM chain (waits for xt) ---
    cudaStreamWaitEvent(s2, evXt, 0);
    gemm_fp16<3, true, false><<<dim3(HW / 128, DD2 / 128, BB), 128, SM3, s2>>>(
        DD2, HW, CC, wp_h, wp_l, CC, 0LL,
        xt_h, xt_l, CC, (long long)HW * CC,
        qpkp, HW, (long long)DD2 * HW, nullptr, nullptr, 0LL, bias2);
    transpose_split_k<<<dim3(HW / 32, DD / 32, BB), dim3(32, 8), 0, s2>>>(
        qpkp, qpt_h, qpt_l, DD, HW, (long long)DD2 * HW, (long long)HW * DD);
    transpose_split_k<<<dim3(HW / 32, DD / 32, BB), dim3(32, 8), 0, s2>>>(
        qpkp + (size_t)DD * HW, kpt_h, kpt_l, DD, HW,
        (long long)DD2 * HW, (long long)HW * DD);
    gemm_fp16<3, true, false><<<dim3(HW / 128, HW / 128, BB), 128, SM3, s2>>>(
        HW, HW, DD, qpt_h, qpt_l, DD, (long long)HW * DD,
        kpt_h, kpt_l, DD, (long long)HW * DD,
        attn_p, HW, (long long)HW * HW, nullptr, nullptr, 0LL, nullptr);
    softmax2304_h_k<<<BB * HW, 256, 0, s2>>>(attn_p, ap_h);
    cudaEventRecord(evPam, s2);

    // ===== join: out_p needs out_c (s1) + attn_p (s2) =====
    cudaStreamWaitEvent(s1, evPam, 0);
    gemm_fp16<1, true, false><<<dim3(HW / 128, OCQ / 128, BB), 128, SM1, s1>>>(
        OCQ, HW, HW, oc_h, nullptr, HW, (long long)OCQ * HW,
        ap_h, nullptr, HW, (long long)HW * HW,
        out_p, HW, (long long)OCQ * HW, nullptr, nullptr, 0LL, nullptr);
}

// round 13
// speedup vs baseline: 1.2671x; 1.1093x over previous
#include <cuda_runtime.h>
#include <cuda_fp16.h>
#include <cstdint>
#include <cstddef>

// ---------------- problem constants ----------------
#define BB   8
#define CC   512
#define HH   48
#define HW   2304     // 48*48
#define HOS  24       // stride-2 output spatial
#define HWS  576      // 24*24
#define NTOT 4608     // BB * HWS (batch-packed conv N, divides 128)
#define KCV  4608     // 512*9 (im2col K)
#define OCQ  1024     // 2C
#define MQK  1536     // combined conv output rows (2C + C)
#define DD   64       // C/8
#define DD2  128      // combined qp+kp rows

// ---------------- scratch (device globals; allocation-free) ----------------
__device__ __align__(128) __half g_col_h[(size_t)NTOT * KCV];
__device__ __align__(128) __half g_col_l[(size_t)NTOT * KCV];
__device__ __align__(128) __half g_wq_h[(size_t)MQK * KCV];
__device__ __align__(128) __half g_wq_l[(size_t)MQK * KCV];
__device__ float  g_bias[MQK];
__device__ __align__(128) __half g_wp_h[(size_t)DD2 * CC];
__device__ __align__(128) __half g_wp_l[(size_t)DD2 * CC];
__device__ float  g_bias2[DD2];
__device__ __align__(128) __half g_qk_h[(size_t)MQK * NTOT];
__device__ __align__(128) __half g_qk_l[(size_t)MQK * NTOT];
__device__ __align__(128) float  g_attn_c[(size_t)BB * OCQ * CC];   // energies
__device__ __align__(128) __half g_ac_h[(size_t)BB * OCQ * CC];
__device__ __align__(128) __half g_ac_l[(size_t)BB * OCQ * CC];
__device__ __align__(128) __half g_xt_h[(size_t)BB * HW * CC];
__device__ __align__(128) __half g_xt_l[(size_t)BB * HW * CC];
__device__ __align__(128) __half g_oc_h[(size_t)BB * OCQ * HW];
__device__ __align__(128) float  g_qpkp[(size_t)BB * DD2 * HW];
__device__ __align__(128) __half g_qpt_h[(size_t)BB * HW * DD];
__device__ __align__(128) __half g_qpt_l[(size_t)BB * HW * DD];
__device__ __align__(128) __half g_kpt_h[(size_t)BB * HW * DD];
__device__ __align__(128) __half g_kpt_l[(size_t)BB * HW * DD];
__device__ __align__(128) float  g_attn_p[(size_t)BB * HW * HW];    // energies
__device__ __align__(128) __half g_ap_h[(size_t)BB * HW * HW];

// ---------------- helpers ----------------
__device__ __forceinline__ void split2(float v, __half& h, __half& l) {
    h = __float2half_rn(v);
    l = __float2half_rn(v - __half2float(h));
}
__device__ __forceinline__ void mma16816(float* c, const uint32_t* a,
                                         uint32_t b0, uint32_t b1) {
    asm volatile(
        "mma.sync.aligned.m16n8k16.row.col.f32.f16.f16.f32 "
        "{%0,%1,%2,%3},{%4,%5,%6,%7},{%8,%9},{%0,%1,%2,%3};"
        : "+f"(c[0]), "+f"(c[1]), "+f"(c[2]), "+f"(c[3])
        : "r"(a[0]), "r"(a[1]), "r"(a[2]), "r"(a[3]), "r"(b0), "r"(b1));
}
__device__ __forceinline__ void ldsm4(uint32_t* r, uint32_t addr) {
    asm volatile("ldmatrix.sync.aligned.m8n8.x4.shared.b16 {%0,%1,%2,%3}, [%4];"
        : "=r"(r[0]), "=r"(r[1]), "=r"(r[2]), "=r"(r[3]) : "r"(addr));
}
#define CP16(dst_u32, src_ptr) \
    asm volatile("cp.async.cg.shared.global [%0], [%1], 16;" :: "r"(dst_u32), "l"(src_ptr))
#define CP_COMMIT() asm volatile("cp.async.commit_group;" ::: "memory")

// ---------------- im2col (3x3 s2 p1) -> split fp16, [b*HWS+p][k], 4 k/thread ----------------
__global__ void im2col_split_k(const float* __restrict__ x) {
    const int KQ = KCV / 4;                       // 1152
    int idx = blockIdx.x * blockDim.x + threadIdx.x;
    int b = blockIdx.y;
    if (idx >= HWS * KQ) return;
    int p  = idx / KQ;
    int k0 = (idx - p * KQ) * 4;
    int oy = p / HOS, ox = p - oy * HOS;
    int iy0 = 2 * oy - 1, ix0 = 2 * ox - 1;
    const float* xb = x + (size_t)b * CC * HW;
    __half h[4], l[4];
    #pragma unroll
    for (int j = 0; j < 4; ++j) {
        int k = k0 + j;
        int ic = k / 9;
        int r  = k - ic * 9;
        int ky = r / 3, kx = r - ky * 3;
        int iy = iy0 + ky, ix = ix0 + kx;
        float v = 0.f;
        if ((unsigned)iy < (unsigned)HH && (unsigned)ix < (unsigned)HH)
            v = xb[((size_t)ic * HH + iy) * HH + ix];
        split2(v, h[j], l[j]);
    }
    size_t d = ((size_t)(b * HWS + p)) * KCV + k0;
    *(__half2*)&g_col_h[d]     = __halves2half2(h[0], h[1]);
    *(__half2*)&g_col_h[d + 2] = __halves2half2(h[2], h[3]);
    *(__half2*)&g_col_l[d]     = __halves2half2(l[0], l[1]);
    *(__half2*)&g_col_l[d + 2] = __halves2half2(l[2], l[3]);
}

// ---------------- elementwise fp32 -> (hi, lo) fp16 (weights) ----------------
__global__ void split_f32_k(const float* __restrict__ s, __half* __restrict__ h,
                            __half* __restrict__ l, long long n) {
    long long i = (long long)blockIdx.x * blockDim.x + threadIdx.x;
    if (i >= n) return;
    __half hh, ll; split2(s[i], hh, ll);
    h[i] = hh; l[i] = ll;
}
__global__ void concat_bias_k(const float* a, const float* b, float* dst,
                              int na, int ntot) {
    int i = blockIdx.x * blockDim.x + threadIdx.x;
    if (i < na) dst[i] = a[i];
    else if (i < ntot) dst[i] = b[i - na];
}

// ---------------- tiled transpose + split: [R][Cn] fp32 -> [Cn][R] hi/lo ----------------
__global__ void transpose_split_k(const float* __restrict__ src,
                                  __half* __restrict__ oh, __half* __restrict__ ol,
                                  int R, int Cn, long long sIn, long long sOut) {
    __shared__ float tile[32][33];
    int b = blockIdx.z;
    src += (long long)b * sIn;
    oh  += (long long)b * sOut;
    ol  += (long long)b * sOut;
    int c0 = blockIdx.x * 32;
    int r0 = blockIdx.y * 32;
    int tx = threadIdx.x, ty = threadIdx.y;
    #pragma unroll
    for (int i = 0; i < 4; ++i)
        tile[ty + 8 * i][tx] = src[(long long)(r0 + ty + 8 * i) * Cn + c0 + tx];
    __syncthreads();
    #pragma unroll
    for (int i = 0; i < 4; ++i) {
        float v = tile[tx][ty + 8 * i];
        __half h, l; split2(v, h, l);
        long long o = (long long)(c0 + ty + 8 * i) * R + r0 + tx;
        oh[o] = h; ol[o] = l;
    }
}

// ---------------- split-fp16 tensor-core GEMM (ldmatrix, 4 warps) ----------------
// C = op(A)@op(B), A,B pre-split hi/lo fp16, stored [rows][K] K-contig.
// TERMS 3: AhBh+AlBh+AhBl ; 2: AhBh+AlBh ; 1: AhBh.
// Tile 128x128, BK=32, 128 threads, m16n8k16.
template <int TERMS, bool OF32, bool OSPLIT>
__global__ void __launch_bounds__(128, 2)
gemm_fp16(int M, int N, int K,
          const __half* __restrict__ Ah, const __half* __restrict__ Al,
          int lda, long long sA,
          const __half* __restrict__ Bh, const __half* __restrict__ Bl,
          int ldb, long long sB,
          float* __restrict__ Cf, int ldc, long long sC,
          __half* __restrict__ Ch, __half* __restrict__ Cl, long long sCh,
          const float* __restrict__ bias)
{
    constexpr int NA = (TERMS >= 2) ? 2 : 1;            // A comps
    constexpr int NB = (TERMS >= 3) ? 2 : 1;            // B comps
    constexpr int NCOMP = NA + NB;
    constexpr int MSZ = 128 * 40;                       // halves per component
    constexpr int SS  = NCOMP * MSZ;                    // halves per stage
    extern __shared__ __half sm[];

    int bz = blockIdx.z;
    Ah += (long long)bz * sA;
    if (TERMS >= 2) Al += (long long)bz * sA;
    Bh += (long long)bz * sB;
    if (TERMS >= 3) Bl += (long long)bz * sB;

    int m0 = blockIdx.y * 128;
    int n0 = blockIdx.x * 128;
    int tid  = threadIdx.x;
    int lane = tid & 31;
    int warp = tid >> 5;
    int wm = (warp >> 1) * 64;
    int wn = (warp & 1) * 64;
    int g = lane >> 2;
    int t = lane & 3;

    uint32_t smbase = (uint32_t)__cvta_generic_to_shared(sm);
    uint32_t a_loff = (uint32_t)(((lane & 7) + ((lane >> 3) & 1) * 8) * 40
                                 + (lane >> 4) * 8);
    uint32_t b_loff = (uint32_t)(((lane & 7) + (lane >> 4) * 8) * 40
                                 + ((lane >> 3) & 1) * 8);

    auto issue = [&](int stage, int k0) {
        #pragma unroll
        for (int j = 0; j < NCOMP * 4; ++j) {
            int q = j * 128 + tid;
            int comp = q >> 9;           // 512 16B-chunks per component
            int w = q & 511;
            int row = w >> 2, seg = w & 3;
            const __half* base;
            int ld, r0;
            if (comp < NA) { ld = lda; r0 = m0; base = (comp == 0) ? Ah : Al; }
            else           { ld = ldb; r0 = n0; base = (comp == NA) ? Bh : Bl; }
            const __half* src = base + (long long)(r0 + row) * ld + k0 + seg * 8;
            uint32_t dst = smbase +
                (uint32_t)(stage * SS + comp * MSZ + row * 40 + seg * 8) * 2;
            CP16(dst, src);
        }
    };

    float acc[4][8][4] = {};
    int nk = K / 32;

    issue(0, 0);
    CP_COMMIT();
    if (nk > 1) issue(1, 32);
    CP_COMMIT();

    for (int i = 0; i < nk; ++i) {
        if (i < nk - 1) asm volatile("cp.async.wait_group 1;" ::: "memory");
        else            asm volatile("cp.async.wait_group 0;" ::: "memory");
        __syncthreads();

        uint32_t st  = smbase + (uint32_t)((i & 1) * SS) * 2;
        uint32_t pAh = st;
        uint32_t pAl = st + (uint32_t)MSZ * 2;              // valid if NA==2
        uint32_t pBh = st + (uint32_t)(NA * MSZ) * 2;
        uint32_t pBl = st + (uint32_t)((NA + 1) * MSZ) * 2; // valid if NB==2

        #pragma unroll
        for (int kk = 0; kk < 32; kk += 16) {
            uint32_t ah[4][4], al[4][4];
            #pragma unroll
            for (int im = 0; im < 4; ++im) {
                uint32_t ro = (uint32_t)((wm + im * 16) * 40 + kk);
                ldsm4(ah[im], pAh + (ro + a_loff) * 2);
                if (TERMS >= 2) ldsm4(al[im], pAl + (ro + a_loff) * 2);
            }
            #pragma unroll
            for (int jp = 0; jp < 4; ++jp) {
                uint32_t co = (uint32_t)((wn + jp * 16) * 40 + kk);
                uint32_t bh[4], bl[4];
                ldsm4(bh, pBh + (co + b_loff) * 2);
                if (TERMS >= 3) ldsm4(bl, pBl + (co + b_loff) * 2);
                #pragma unroll
                for (int im = 0; im < 4; ++im) {
                    mma16816(acc[im][2 * jp],     ah[im], bh[0], bh[1]);
                    mma16816(acc[im][2 * jp + 1], ah[im], bh[2], bh[3]);
                    if (TERMS >= 2) {
                        mma16816(acc[im][2 * jp],     al[im], bh[0], bh[1]);
                        mma16816(acc[im][2 * jp + 1], al[im], bh[2], bh[3]);
                    }
                    if (TERMS >= 3) {
                        mma16816(acc[im][2 * jp],     ah[im], bl[0], bl[1]);
                        mma16816(acc[im][2 * jp + 1], ah[im], bl[2], bl[3]);
                    }
                }
            }
        }
        __syncthreads();
        if (i + 2 < nk) {
            issue((i + 2) & 1, (i + 2) * 32);
            CP_COMMIT();
        }
    }

    // ---------------- epilogue ----------------
    #pragma unroll
    for (int im = 0; im < 4; ++im) {
        int mr = m0 + wm + im * 16 + g;
        float bi0 = bias ? bias[mr] : 0.f;
        float bi1 = bias ? bias[mr + 8] : 0.f;
        #pragma unroll
        for (int jn = 0; jn < 8; ++jn) {
            int nc = n0 + wn + jn * 8 + 2 * t;
            float v00 = acc[im][jn][0] + bi0, v01 = acc[im][jn][1] + bi0;
            float v10 = acc[im][jn][2] + bi1, v11 = acc[im][jn][3] + bi1;
            if (OF32) {
                float* c0 = Cf + (long long)bz * sC + (long long)mr * ldc + nc;
                float* c1 = Cf + (long long)bz * sC + (long long)(mr + 8) * ldc + nc;
                *(float2*)c0 = make_float2(v00, v01);
                *(float2*)c1 = make_float2(v10, v11);
            }
            if (OSPLIT) {
                long long o0 = (long long)bz * sCh + (long long)mr * ldc + nc;
                long long o1 = (long long)bz * sCh + (long long)(mr + 8) * ldc + nc;
                if (Cl) {
                    __half h00, l00, h01, l01, h10, l10, h11, l11;
                    split2(v00, h00, l00); split2(v01, h01, l01);
                    split2(v10, h10, l10); split2(v11, h11, l11);
                    *(__half2*)&Ch[o0] = __halves2half2(h00, h01);
                    *(__half2*)&Cl[o0] = __halves2half2(l00, l01);
                    *(__half2*)&Ch[o1] = __halves2half2(h10, h11);
                    *(__half2*)&Cl[o1] = __halves2half2(l10, l11);
                } else {
                    *(__half2*)&Ch[o0] = __halves2half2(__float2half_rn(v00),
                                                        __float2half_rn(v01));
                    *(__half2*)&Ch[o1] = __halves2half2(__float2half_rn(v10),
                                                        __float2half_rn(v11));
                }
            }
        }
    }
}

// ---------------- fused softmax(-E) rows of 512 + split ----------------
__global__ void softmax_neg512_split_k(const float* __restrict__ e,
                                       __half* __restrict__ oh,
                                       __half* __restrict__ ol, int nrows) {
    int row  = blockIdx.x * 8 + (threadIdx.x >> 5);
    int lane = threadIdx.x & 31;
    if (row >= nrows) return;
    const float* p = e + (long long)row * CC + lane * 16;
    float v[16];
    float mx = -3.4e38f;
    #pragma unroll
    for (int q = 0; q < 4; ++q) {
        float4 f = *(const float4*)(p + 4 * q);
        v[4 * q + 0] = -f.x; v[4 * q + 1] = -f.y;
        v[4 * q + 2] = -f.z; v[4 * q + 3] = -f.w;
    }
    #pragma unroll
    for (int j = 0; j < 16; ++j) mx = fmaxf(mx, v[j]);
    #pragma unroll
    for (int o = 16; o; o >>= 1) mx = fmaxf(mx, __shfl_xor_sync(0xffffffffu, mx, o));
    float s = 0.f;
    #pragma unroll
    for (int j = 0; j < 16; ++j) { v[j] = __expf(v[j] - mx); s += v[j]; }
    #pragma unroll
    for (int o = 16; o; o >>= 1) s += __shfl_xor_sync(0xffffffffu, s, o);
    float inv = 1.f / s;
    long long off = (long long)row * CC + lane * 16;
    #pragma unroll
    for (int j = 0; j < 16; j += 2) {
        __half h0, l0, h1, l1;
        split2(v[j] * inv, h0, l0);
        split2(v[j + 1] * inv, h1, l1);
        *(__half2*)&oh[off + j] = __halves2half2(h0, h1);
        *(__half2*)&ol[off + j] = __halves2half2(l0, l1);
    }
}

// ---------------- fused softmax rows of 2304 -> fp16 (hi only) ----------------
__global__ void __launch_bounds__(256)
softmax2304_h_k(const float* __restrict__ e, __half* __restrict__ oh) {
    __shared__ float redm[8];
    __shared__ float reds[8];
    int tn = threadIdx.x;
    const float* p = e + (size_t)blockIdx.x * HW;
    float v[9];
    float mx = -3.4e38f;
    #pragma unroll
    for (int j = 0; j < 9; ++j) {
        v[j] = p[tn + 256 * j];
        mx = fmaxf(mx, v[j]);
    }
    #pragma unroll
    for (int o = 16; o; o >>= 1) mx = fmaxf(mx, __shfl_xor_sync(0xffffffffu, mx, o));
    if ((tn & 31) == 0) redm[tn >> 5] = mx;
    __syncthreads();
    mx = redm[0];
    #pragma unroll
    for (int i = 1; i < 8; ++i) mx = fmaxf(mx, redm[i]);
    float s = 0.f;
    #pragma unroll
    for (int j = 0; j < 9; ++j) { v[j] = __expf(v[j] - mx); s += v[j]; }
    #pragma unroll
    for (int o = 16; o; o >>= 1) s += __shfl_xor_sync(0xffffffffu, s, o);
    if ((tn & 31) == 0) reds[tn >> 5] = s;
    __syncthreads();
    s = reds[0];
    #pragma unroll
    for (int i = 1; i < 8; ++i) s += reds[i];
    float inv = 1.f / s;
    size_t off = (size_t)blockIdx.x * HW + tn;
    #pragma unroll
    for (int j = 0; j < 9; ++j)
        oh[off + 256 * j] = __float2half_rn(v[j] * inv);
}

// ---------------- launch ----------------
extern "C" void kernel_launch(void* const* d_in, const int* in_sizes, int n_in,
                              void* d_out, int out_size) {
    const float* x   = (const float*)d_in[0];
    const float* Wqc = (const float*)d_in[1];
    const float* bqc = (const float*)d_in[2];
    const float* Wkc = (const float*)d_in[3];
    const float* bkc = (const float*)d_in[4];
    const float* Wqp = (const float*)d_in[5];
    const float* bqp = (const float*)d_in[6];
    const float* Wkp = (const float*)d_in[7];
    const float* bkp = (const float*)d_in[8];

    float* out   = (float*)d_out;
    float* out_c = out;                              // (B, 2C, HW)
    float* out_p = out + (size_t)BB * OCQ * HW;      // (B, 2C, H, W)

    __half *col_h, *col_l, *wq_h, *wq_l, *wp_h, *wp_l, *qk_h, *qk_l;
    __half *ac_h, *ac_l, *xt_h, *xt_l, *oc_h, *qpt_h, *qpt_l, *kpt_h, *kpt_l, *ap_h;
    float *bias, *bias2, *attn_c, *qpkp, *attn_p;
    cudaGetSymbolAddress((void**)&col_h, g_col_h);
    cudaGetSymbolAddress((void**)&col_l, g_col_l);
    cudaGetSymbolAddress((void**)&wq_h,  g_wq_h);
    cudaGetSymbolAddress((void**)&wq_l,  g_wq_l);
    cudaGetSymbolAddress((void**)&wp_h,  g_wp_h);
    cudaGetSymbolAddress((void**)&wp_l,  g_wp_l);
    cudaGetSymbolAddress((void**)&bias,  g_bias);
    cudaGetSymbolAddress((void**)&bias2, g_bias2);
    cudaGetSymbolAddress((void**)&qk_h,  g_qk_h);
    cudaGetSymbolAddress((void**)&qk_l,  g_qk_l);
    cudaGetSymbolAddress((void**)&attn_c, g_attn_c);
    cudaGetSymbolAddress((void**)&ac_h,  g_ac_h);
    cudaGetSymbolAddress((void**)&ac_l,  g_ac_l);
    cudaGetSymbolAddress((void**)&xt_h,  g_xt_h);
    cudaGetSymbolAddress((void**)&xt_l,  g_xt_l);
    cudaGetSymbolAddress((void**)&oc_h,  g_oc_h);
    cudaGetSymbolAddress((void**)&qpkp,  g_qpkp);
    cudaGetSymbolAddress((void**)&qpt_h, g_qpt_h);
    cudaGetSymbolAddress((void**)&qpt_l, g_qpt_l);
    cudaGetSymbolAddress((void**)&kpt_h, g_kpt_h);
    cudaGetSymbolAddress((void**)&kpt_l, g_kpt_l);
    cudaGetSymbolAddress((void**)&attn_p, g_attn_p);
    cudaGetSymbolAddress((void**)&ap_h,  g_ap_h);

    const int SM3 = 2 * 4 * 128 * 40 * 2;   // 81920 B (TERMS=3)
    const int SM2 = 2 * 3 * 128 * 40 * 2;   // 61440 B (TERMS=2)
    const int SM1 = 2 * 2 * 128 * 40 * 2;   // 40960 B (TERMS=1)
    cudaFuncSetAttribute(gemm_fp16<3, false, true>,
                         cudaFuncAttributeMaxDynamicSharedMemorySize, SM3);
    cudaFuncSetAttribute(gemm_fp16<3, true, false>,
                         cudaFuncAttributeMaxDynamicSharedMemorySize, SM3);
    cudaFuncSetAttribute(gemm_fp16<2, true, true>,
                         cudaFuncAttributeMaxDynamicSharedMemorySize, SM2);
    cudaFuncSetAttribute(gemm_fp16<1, true, false>,
                         cudaFuncAttributeMaxDynamicSharedMemorySize, SM1);

    // --- one-time stream/event infra (host-side, no device allocation) ---
    static cudaStream_t s2 = nullptr;
    static cudaEvent_t evStart = nullptr, evXt = nullptr, evW = nullptr,
                       evPam = nullptr;
    if (!s2) {
        cudaStreamCreateWithFlags(&s2, cudaStreamNonBlocking);
        cudaEventCreateWithFlags(&evStart, cudaEventDisableTiming);
        cudaEventCreateWithFlags(&evXt,    cudaEventDisableTiming);
        cudaEventCreateWithFlags(&evW,     cudaEventDisableTiming);
        cudaEventCreateWithFlags(&evPam,   cudaEventDisableTiming);
    }
    cudaStream_t s1 = 0;   // default stream (captured by harness)

    // ===== fork =====
    cudaEventRecord(evStart, s1);
    cudaStreamWaitEvent(s2, evStart, 0);

    // --- s2: all weight prep (overlaps with im2col/transpose on s1) ---
    split_f32_k<<<((long long)OCQ * KCV + 255) / 256, 256, 0, s2>>>(
        Wqc, wq_h, wq_l, (long long)OCQ * KCV);
    split_f32_k<<<((long long)CC * KCV + 255) / 256, 256, 0, s2>>>(
        Wkc, wq_h + (size_t)OCQ * KCV, wq_l + (size_t)OCQ * KCV,
        (long long)CC * KCV);
    concat_bias_k<<<(MQK + 255) / 256, 256, 0, s2>>>(bqc, bkc, bias, OCQ, MQK);
    cudaEventRecord(evW, s2);          // conv weights ready
    split_f32_k<<<(DD * CC + 255) / 256, 256, 0, s2>>>(Wqp, wp_h, wp_l, DD * CC);
    split_f32_k<<<(DD * CC + 255) / 256, 256, 0, s2>>>(
        Wkp, wp_h + (size_t)DD * CC, wp_l + (size_t)DD * CC, DD * CC);
    concat_bias_k<<<1, 128, 0, s2>>>(bqp, bkp, bias2, DD, DD2);

    // --- s1: data prep ---
    im2col_split_k<<<dim3((HWS * (KCV / 4) + 255) / 256, BB), 256, 0, s1>>>(x);
    transpose_split_k<<<dim3(HW / 32, CC / 32, BB), dim3(32, 8), 0, s1>>>(
        x, xt_h, xt_l, CC, HW, (long long)CC * HW, (long long)CC * HW);
    cudaEventRecord(evXt, s1);                 // xt ready for PAM

    // --- s1: CAM chain ---
    cudaStreamWaitEvent(s1, evW, 0);
    // combined conv, batch-packed: qk[1536,4608] = W @ col^T + bias -> split
    gemm_fp16<3, false, true><<<dim3(NTOT / 128, MQK / 128, 1), 128, SM3, s1>>>(
        MQK, NTOT, KCV, wq_h, wq_l, KCV, 0LL,
        col_h, col_l, KCV, 0LL,
        nullptr, NTOT, 0LL, qk_h, qk_l, 0LL, bias);
    // energy = qc @ kc^T per batch via lda/offset slicing (K=576)
    gemm_fp16<3, true, false><<<dim3(CC / 128, OCQ / 128, BB), 128, SM3, s1>>>(
        OCQ, CC, HWS,
        qk_h, qk_l, NTOT, (long long)HWS,
        qk_h + (size_t)OCQ * NTOT, qk_l + (size_t)OCQ * NTOT, NTOT,
        (long long)HWS,
        attn_c, CC, (long long)OCQ * CC, nullptr, nullptr, 0LL, nullptr);
    softmax_neg512_split_k<<<(BB * OCQ) / 8, 256, 0, s1>>>(attn_c, ac_h, ac_l,
                                                           BB * OCQ);
    // out_c = attn_c @ xf, 2-term (drop xt_l) -> fp32 (d_out) + hi fp16
    gemm_fp16<2, true, true><<<dim3(HW / 128, OCQ / 128, BB), 128, SM2, s1>>>(
        OCQ, HW, CC, ac_h, ac_l, CC, (long long)OCQ * CC,
        xt_h, nullptr, CC, (long long)HW * CC,
        out_c, HW, (long long)OCQ * HW,
        oc_h, nullptr, (long long)OCQ * HW, nullptr);

    // --- s2: PAM chain (waits for xt) ---
    cudaStreamWaitEvent(s2, evXt, 0);
    gemm_fp16<3, true, false><<<dim3(HW / 128, DD2 / 128, BB), 128, SM3, s2>>>(
        DD2, HW, CC, wp_h, wp_l, CC, 0LL,
        xt_h, xt_l, CC, (long long)HW * CC,
        qpkp, HW, (long long)DD2 * HW, nullptr, nullptr, 0LL, bias2);
    transpose_split_k<<<dim3(HW / 32, DD / 32, BB), dim3(32, 8), 0, s2>>>(
        qpkp, qpt_h, qpt_l, DD, HW, (long long)DD2 * HW, (long long)HW * DD);
    transpose_split_k<<<dim3(HW / 32, DD / 32, BB), dim3(32, 8), 0, s2>>>(
        qpkp + (size_t)DD * HW, kpt_h, kpt_l, DD, HW,
        (long long)DD2 * HW, (long long)HW * DD);
    gemm_fp16<3, true, false><<<dim3(HW / 128, HW / 128, BB), 128, SM3, s2>>>(
        HW, HW, DD, qpt_h, qpt_l, DD, (long long)HW * DD,
        kpt_h, kpt_l, DD, (long long)HW * DD,
        attn_p, HW, (long long)HW * HW, nullptr, nullptr, 0LL, nullptr);
    softmax2304_h_k<<<BB * HW, 256, 0, s2>>>(attn_p, ap_h);
    cudaEventRecord(evPam, s2);

    // ===== join: out_p needs out_c (s1) + attn_p (s2) =====
    cudaStreamWaitEvent(s1, evPam, 0);
    gemm_fp16<1, true, false><<<dim3(HW / 128, OCQ / 128, BB), 128, SM1, s1>>>(
        OCQ, HW, HW, oc_h, nullptr, HW, (long long)OCQ * HW,
        ap_h, nullptr, HW, (long long)HW * HW,
        out_p, HW, (long long)OCQ * HW, nullptr, nullptr, 0LL, nullptr);
}